// round 14
// baseline (speedup 1.0000x reference)
#include <cuda_runtime.h>
#include <cuda_fp16.h>
#include <cstdint>
#include <math.h>

// Problem constants
#define S_LEN 4096
#define D_MODEL 512
#define SLOPE 0.5f
#define QT 32
#define NKEY 96
#define WBACK 64
#define NB 4

// Scratch
__device__ __half g_Xh[NB * S_LEN * D_MODEL];   // X fp16 (attn K; written by GEMM)
__device__ __half g_Qh[NB * S_LEN * D_MODEL];   // Q fp16
__device__ __half g_Vh[NB * S_LEN * D_MODEL];   // V fp16 (+bias)
__device__ __half g_Wh[1024 * 512];             // [Wqk | Wv^T] fp16, [n][k]

// ---------------------------------------------------------------------------
// Helpers
// ---------------------------------------------------------------------------
__device__ __forceinline__ void mma16816h(float* d, const uint32_t* a,
                                          uint32_t b0, uint32_t b1)
{
    asm volatile(
        "mma.sync.aligned.m16n8k16.row.col.f32.f16.f16.f32 "
        "{%0,%1,%2,%3}, {%4,%5,%6,%7}, {%8,%9}, {%0,%1,%2,%3};"
        : "+f"(d[0]), "+f"(d[1]), "+f"(d[2]), "+f"(d[3])
        : "r"(a[0]), "r"(a[1]), "r"(a[2]), "r"(a[3]), "r"(b0), "r"(b1));
}

__device__ __forceinline__ void ldsm_x4_trans(uint32_t& r0, uint32_t& r1,
                                              uint32_t& r2, uint32_t& r3,
                                              uint32_t addr)
{
    asm volatile(
        "ldmatrix.sync.aligned.m8n8.x4.trans.shared.b16 {%0,%1,%2,%3}, [%4];"
        : "=r"(r0), "=r"(r1), "=r"(r2), "=r"(r3) : "r"(addr));
}

__device__ __forceinline__ void cpa16(uint32_t dst, const void* src) {
    asm volatile("cp.async.cg.shared.global [%0], [%1], 16;"
                 :: "r"(dst), "l"(src) : "memory");
}
__device__ __forceinline__ void sts_zero16(uint32_t dst) {
    asm volatile("st.shared.v4.b32 [%0], {%1,%1,%1,%1};" :: "r"(dst), "r"(0u)
                 : "memory");
}
#define CPA_COMMIT() asm volatile("cp.async.commit_group;" ::: "memory")
#define CPA_WAIT0()  asm volatile("cp.async.wait_group 0;" ::: "memory")

// ---------------------------------------------------------------------------
// pack_w: [Wqk | Wv^T] -> fp16 (g_Wh, [n][k])
// ---------------------------------------------------------------------------
__global__ void pack_w(const float* __restrict__ Wqk,
                       const float* __restrict__ Wv)
{
    int idx = blockIdx.x * 256 + threadIdx.x;   // 0..524287
    int n = idx >> 9, k = idx & 511;
    float w = (n < 512) ? Wqk[k * 512 + n] : Wv[(n - 512) * 512 + k];
    g_Wh[idx] = __float2half_rn(w);
}

// ---------------------------------------------------------------------------
// fp16 mma GEMM: [Q|V][16384, 1024] = X[16384,512] @ Wh^T, m16n8k16.
// Reads fp32 X, converts in-register; n0==0 CTAs also emit g_Xh.
// Q written fp16 (g_Qh); V written fp16 + bias (g_Vh).
// ---------------------------------------------------------------------------
#define GSTR 36
#define GPLANE (128 * GSTR)

__global__ __launch_bounds__(256)
void mma_gemm(const float* __restrict__ X, const float* __restrict__ bias,
              __half* __restrict__ Qh, __half* __restrict__ Vh)
{
    extern __shared__ uint32_t smw[];
    uint32_t* sA = smw;
    uint32_t* sB = smw + GPLANE;

    const int tid = threadIdx.x;
    const int wid = tid >> 5;
    const int lane = tid & 31;
    const int g = lane >> 2;
    const int t4 = lane & 3;
    const int warp_m = wid & 3;
    const int warp_n = wid >> 2;
    const int m0 = blockIdx.x * 128;
    const int n0 = blockIdx.y * 128;
    const bool emit_xh = (blockIdx.y == 0);

    float acc[2][8][4];
#pragma unroll
    for (int mt = 0; mt < 2; mt++)
#pragma unroll
        for (int nt = 0; nt < 8; nt++)
#pragma unroll
            for (int i = 0; i < 4; i++) acc[mt][nt][i] = 0.f;

    for (int c = 0; c < 8; c++) {
        const int k0 = c * 64;     // in elements
        float4 af[4][2];
        uint4  bv[4];
#pragma unroll
        for (int i = 0; i < 4; i++) {
            int idx = tid + 256 * i;
            int row = idx >> 3, h8 = (idx & 7) * 8;
            const float* src = &X[(size_t)(m0 + row) * 512 + k0 + h8];
            af[i][0] = *reinterpret_cast<const float4*>(src);
            af[i][1] = *reinterpret_cast<const float4*>(src + 4);
            bv[i] = *reinterpret_cast<const uint4*>(
                &g_Wh[(size_t)(n0 + row) * 512 + k0 + h8]);
        }
        if (c) __syncthreads();
#pragma unroll
        for (int i = 0; i < 4; i++) {
            int idx = tid + 256 * i;
            int row = idx >> 3, w4 = (idx & 7) * 4;
            __half2 p0 = __floats2half2_rn(af[i][0].x, af[i][0].y);
            __half2 p1 = __floats2half2_rn(af[i][0].z, af[i][0].w);
            __half2 p2 = __floats2half2_rn(af[i][1].x, af[i][1].y);
            __half2 p3 = __floats2half2_rn(af[i][1].z, af[i][1].w);
            uint4 at = make_uint4(*(uint32_t*)&p0, *(uint32_t*)&p1,
                                  *(uint32_t*)&p2, *(uint32_t*)&p3);
            *reinterpret_cast<uint4*>(&sA[row * GSTR + w4]) = at;
            *reinterpret_cast<uint4*>(&sB[row * GSTR + w4]) = bv[i];
            if (emit_xh)
                *reinterpret_cast<uint4*>(
                    &g_Xh[(size_t)(m0 + row) * 512 + k0 + w4 * 2]) = at;
        }
        __syncthreads();

#pragma unroll
        for (int s = 0; s < 4; s++) {
            const int kc = s * 8 + t4;
            uint32_t a[2][4];
#pragma unroll
            for (int mt = 0; mt < 2; mt++) {
                int r = warp_m * 32 + mt * 16 + g;
                a[mt][0] = sA[r * GSTR + kc];
                a[mt][1] = sA[(r + 8) * GSTR + kc];
                a[mt][2] = sA[r * GSTR + kc + 4];
                a[mt][3] = sA[(r + 8) * GSTR + kc + 4];
            }
#pragma unroll
            for (int nt = 0; nt < 8; nt++) {
                int rn = warp_n * 64 + nt * 8 + g;
                uint32_t b0 = sB[rn * GSTR + kc];
                uint32_t b1 = sB[rn * GSTR + kc + 4];
#pragma unroll
                for (int mt = 0; mt < 2; mt++)
                    mma16816h(acc[mt][nt], a[mt], b0, b1);
            }
        }
    }

#pragma unroll
    for (int mt = 0; mt < 2; mt++) {
        int row0 = m0 + warp_m * 32 + mt * 16 + g;
#pragma unroll
        for (int nt = 0; nt < 8; nt++) {
            int col = n0 + warp_n * 64 + nt * 8 + t4 * 2;
            if (col < 512) {
                __half2 lo = __floats2half2_rn(acc[mt][nt][0], acc[mt][nt][1]);
                __half2 hi = __floats2half2_rn(acc[mt][nt][2], acc[mt][nt][3]);
                *reinterpret_cast<uint32_t*>(&Qh[(size_t)row0 * 512 + col]) =
                    *(uint32_t*)&lo;
                *reinterpret_cast<uint32_t*>(&Qh[(size_t)(row0 + 8) * 512 + col]) =
                    *(uint32_t*)&hi;
            } else {
                int vc = col - 512;
                float2 b2 = *reinterpret_cast<const float2*>(&bias[vc]);
                __half2 lo = __floats2half2_rn(acc[mt][nt][0] + b2.x,
                                               acc[mt][nt][1] + b2.y);
                __half2 hi = __floats2half2_rn(acc[mt][nt][2] + b2.x,
                                               acc[mt][nt][3] + b2.y);
                *reinterpret_cast<uint32_t*>(&Vh[(size_t)row0 * 512 + vc]) =
                    *(uint32_t*)&lo;
                *reinterpret_cast<uint32_t*>(&Vh[(size_t)(row0 + 8) * 512 + vc]) =
                    *(uint32_t*)&hi;
            }
        }
    }
}

// ---------------------------------------------------------------------------
// Windowed attention, all-fp16 MMA, band = 96 keys (WBACK 64).
// CTA = 32 q x 96-key band, 8 warps (2m x 4n; 24 cols per n-warp).
// Phase1: fp16 QK^T, 64-col double-buffered chunks.
// Phase2: softmax (8 lanes x 12 cols); P packed fp16 pairs into sPh.
// Phase3: fp16 PV via ldmatrix.x4.trans, 6 k16 steps, double-buffered V.
// ---------------------------------------------------------------------------
#define SP_STR 100
#define PH_STR 52              // sPh row stride in words (48 pairs + pad)
#define HQ_STR 36              // phase-1 fp16 chunk row stride (words)
#define VH_STR 72              // phase-3 V row stride in halves
#define W_PH 3200
#define W_Q0 4864
#define W_K0 (W_Q0 + 32 * HQ_STR)        // 6016
#define W_Q1 (W_K0 + 96 * HQ_STR)        // 9472
#define W_K1 (W_Q1 + 32 * HQ_STR)        // 10624
#define W_V0 4864                        // aliased over phase-1 buffers
#define W_V1 (W_V0 + 96 * (VH_STR / 2))  // 8320
#define ATTN_W (W_K1 + 96 * HQ_STR)      // 14080 words = 56320 B

__global__ __launch_bounds__(256, 2)
void attn_tc(float* __restrict__ O)
{
    extern __shared__ uint32_t smw[];
    float* sP = reinterpret_cast<float*>(smw);
    uint32_t* sPh = smw + W_PH;
    const uint32_t sbase = (uint32_t)__cvta_generic_to_shared(smw);

    const int tid = threadIdx.x;
    const int wid = tid >> 5;
    const int lane = tid & 31;
    const int g = lane >> 2;
    const int t4 = lane & 3;
    const int b  = blockIdx.y;
    const int i0 = blockIdx.x * QT;
    const int jstart = i0 - WBACK;

    const __half* Qb = g_Qh + (size_t)b * S_LEN * D_MODEL;
    const __half* Kb = g_Xh + (size_t)b * S_LEN * D_MODEL;
    const __half* Vb = g_Vh + (size_t)b * S_LEN * D_MODEL;

    const int wm = wid & 1;
    const int wn = wid >> 1;      // 0..3 -> 24 score cols each

    const int qrow = tid >> 3;            // 0..31
    const int qu4  = tid & 7;

    // prologue: phase-1 chunk 0 (Q 32 rows, K 96 rows x 64 halves)
    {
        cpa16(sbase + (W_Q0 + qrow * HQ_STR + qu4 * 4) * 4,
              &Qb[(size_t)(i0 + qrow) * 512 + 0 + qu4 * 8]);
#pragma unroll
        for (int i = 0; i < 3; i++) {
            int idx = tid + 256 * i;      // 768 = 96 x 8
            int row = idx >> 3, u4 = idx & 7;
            int j = jstart + row;
            uint32_t dst = sbase + (W_K0 + row * HQ_STR + u4 * 4) * 4;
            if (j >= 0) cpa16(dst, &Kb[(size_t)j * 512 + 0 + u4 * 8]);
            else sts_zero16(dst);
        }
        CPA_COMMIT();
    }

    float accs[3][4];
#pragma unroll
    for (int nt = 0; nt < 3; nt++)
#pragma unroll
        for (int i = 0; i < 4; i++) accs[nt][i] = 0.f;

    for (int c = 0; c < 8; c++) {
        CPA_WAIT0();
        __syncthreads();
        if (c < 7) {
            const int k0 = (c + 1) * 64;
            const int wq = ((c + 1) & 1) ? W_Q1 : W_Q0;
            const int wk = ((c + 1) & 1) ? W_K1 : W_K0;
            cpa16(sbase + (wq + qrow * HQ_STR + qu4 * 4) * 4,
                  &Qb[(size_t)(i0 + qrow) * 512 + k0 + qu4 * 8]);
#pragma unroll
            for (int i = 0; i < 3; i++) {
                int idx = tid + 256 * i;
                int row = idx >> 3, u4 = idx & 7;
                int j = jstart + row;
                uint32_t dst = sbase + (wk + row * HQ_STR + u4 * 4) * 4;
                if (j >= 0) cpa16(dst, &Kb[(size_t)j * 512 + k0 + u4 * 8]);
                else sts_zero16(dst);
            }
            CPA_COMMIT();
        }
        const uint32_t* sQ = smw + ((c & 1) ? W_Q1 : W_Q0);
        const uint32_t* sK = smw + ((c & 1) ? W_K1 : W_K0);
#pragma unroll
        for (int s = 0; s < 4; s++) {
            const int kc = s * 8 + t4;
            uint32_t a[4];
            int r = wm * 16 + g;
            a[0] = sQ[r * HQ_STR + kc];
            a[1] = sQ[(r + 8) * HQ_STR + kc];
            a[2] = sQ[r * HQ_STR + kc + 4];
            a[3] = sQ[(r + 8) * HQ_STR + kc + 4];
#pragma unroll
            for (int nt = 0; nt < 3; nt++) {
                int rn = wn * 24 + nt * 8 + g;
                uint32_t b0 = sK[rn * HQ_STR + kc];
                uint32_t b1 = sK[rn * HQ_STR + kc + 4];
                mma16816h(accs[nt], a, b0, b1);
            }
        }
    }

    // scale + ALiBi + causal mask -> sP (fp32)
    const float scale = 0.04419417382415922f;
#pragma unroll
    for (int nt = 0; nt < 3; nt++) {
#pragma unroll
        for (int h = 0; h < 2; h++) {
            int row = wm * 16 + g + 8 * h;
            int i = i0 + row;
#pragma unroll
            for (int cp = 0; cp < 2; cp++) {
                int col = wn * 24 + nt * 8 + t4 * 2 + cp;
                int j = jstart + col;
                float v = accs[nt][h * 2 + cp];
                float s = (j < 0 || j > i) ? -1e30f
                        : v * scale + SLOPE * (float)(j - i);
                sP[row * SP_STR + col] = s;
            }
        }
    }
    __syncthreads();

    // ---- issue V chunk 0 (fp16, overlaps softmax) ----
    {
#pragma unroll
        for (int i = 0; i < 3; i++) {
            int idx = tid + 256 * i;          // 768 = 96 rows x 8
            int row = idx >> 3, u4 = idx & 7;
            int j = jstart + row;
            uint32_t dst = sbase + W_V0 * 4 + (row * VH_STR + u4 * 8) * 2;
            if (j >= 0) cpa16(dst, &Vb[(size_t)j * 512 + 0 + u4 * 8]);
            else sts_zero16(dst);
        }
        CPA_COMMIT();
    }

    // ---- softmax (96 cols: 8 lanes x 12); pack P fp16 pairs in sPh ----
    {
        int r = tid >> 3;
        int l = tid & 7;
        float* row = &sP[r * SP_STR];
        float m = -1e30f;
#pragma unroll
        for (int k = 0; k < 12; k++) m = fmaxf(m, row[l * 12 + k]);
#pragma unroll
        for (int o = 4; o > 0; o >>= 1)
            m = fmaxf(m, __shfl_xor_sync(0xffffffffu, m, o));
        float sum = 0.f;
        float e[12];
#pragma unroll
        for (int k = 0; k < 12; k++) {
            e[k] = __expf(row[l * 12 + k] - m);
            sum += e[k];
        }
#pragma unroll
        for (int o = 4; o > 0; o >>= 1)
            sum += __shfl_xor_sync(0xffffffffu, sum, o);
        float inv = 1.f / sum;
#pragma unroll
        for (int k = 0; k < 6; k++) {
            __half2 h2 = __floats2half2_rn(e[2 * k] * inv, e[2 * k + 1] * inv);
            sPh[r * PH_STR + l * 6 + k] = *(uint32_t*)&h2;
        }
    }
    __syncthreads();

    // ---- P fragments -> registers (6 k16 steps over 96 keys) ----
    uint32_t pa[6][4];
    {
        int r = wm * 16 + g;
#pragma unroll
        for (int s = 0; s < 6; s++) {
            int kc = s * 8 + t4;
            pa[s][0] = sPh[r * PH_STR + kc];
            pa[s][1] = sPh[(r + 8) * PH_STR + kc];
            pa[s][2] = sPh[r * PH_STR + kc + 4];
            pa[s][3] = sPh[(r + 8) * PH_STR + kc + 4];
        }
    }

    // ---- phase 3: O = P @ V (fp16 via ldmatrix.trans) ----
    const int wn8 = wid >> 1;          // 0..3 -> 16 features
    const int lrow = lane & 15;
    const int lcolg = (lane >> 4) * 8;

    for (int ch = 0; ch < 8; ch++) {
        CPA_WAIT0();
        __syncthreads();
        if (ch < 7) {
            const int e0 = (ch + 1) * 64;
            const int wv = ((ch + 1) & 1) ? W_V1 : W_V0;
#pragma unroll
            for (int i = 0; i < 3; i++) {
                int idx = tid + 256 * i;
                int row = idx >> 3, u4 = idx & 7;
                int j = jstart + row;
                uint32_t dst = sbase + wv * 4 + (row * VH_STR + u4 * 8) * 2;
                if (j >= 0) cpa16(dst, &Vb[(size_t)j * 512 + e0 + u4 * 8]);
                else sts_zero16(dst);
            }
            CPA_COMMIT();
        }
        const uint32_t vbase = sbase + ((ch & 1) ? W_V1 : W_V0) * 4;

        float acco[2][4];
#pragma unroll
        for (int nt = 0; nt < 2; nt++)
#pragma unroll
            for (int i = 0; i < 4; i++) acco[nt][i] = 0.f;

#pragma unroll
        for (int s = 0; s < 6; s++) {          // k16 over 96 tokens
            uint32_t r0, r1, r2, r3;
            uint32_t addr = vbase +
                ((s * 16 + lrow) * VH_STR + wn8 * 16 + lcolg) * 2;
            ldsm_x4_trans(r0, r1, r2, r3, addr);
            mma16816h(acco[0], pa[s], r0, r1);
            mma16816h(acco[1], pa[s], r2, r3);
        }

        const int e0 = ch * 64;
#pragma unroll
        for (int nt = 0; nt < 2; nt++) {
            int col = e0 + wn8 * 16 + nt * 8 + t4 * 2;
            int row0 = i0 + wm * 16 + g;
            *reinterpret_cast<float2*>(
                &O[((size_t)b * S_LEN + row0) * 512 + col]) =
                make_float2(acco[nt][0], acco[nt][1]);
            *reinterpret_cast<float2*>(
                &O[((size_t)b * S_LEN + row0 + 8) * 512 + col]) =
                make_float2(acco[nt][2], acco[nt][3]);
        }
    }
}

// ---------------------------------------------------------------------------
extern "C" void kernel_launch(void* const* d_in, const int* in_sizes, int n_in,
                              void* d_out, int out_size)
{
    const float* x   = (const float*)d_in[0];
    const float* Wqk = (const float*)d_in[1];
    const float* Wv  = (const float*)d_in[2];
    const float* bv  = (const float*)d_in[3];
    float* out = (float*)d_out;

    __half *Qhp = nullptr, *Vhp = nullptr;
    cudaGetSymbolAddress((void**)&Qhp, g_Qh);
    cudaGetSymbolAddress((void**)&Vhp, g_Vh);

    const int gemm_smem = 2 * GPLANE * 4;   // 36864 B
    cudaFuncSetAttribute(mma_gemm, cudaFuncAttributeMaxDynamicSharedMemorySize,
                         gemm_smem);
    const int attn_smem = ATTN_W * 4;       // 56320 B
    cudaFuncSetAttribute(attn_tc, cudaFuncAttributeMaxDynamicSharedMemorySize,
                         attn_smem);

    pack_w<<<2048, 256>>>(Wqk, Wv);

    dim3 ggemm(128, 8);
    mma_gemm<<<ggemm, 256, gemm_smem>>>(x, bv, Qhp, Vhp);

    dim3 gattn(S_LEN / QT, NB);
    attn_tc<<<gattn, 256, attn_smem>>>(out);
}

// round 16
// speedup vs baseline: 1.5848x; 1.5848x over previous
#include <cuda_runtime.h>
#include <cuda_fp16.h>
#include <cstdint>
#include <math.h>

// Problem constants
#define S_LEN 4096
#define D_MODEL 512
#define SLOPE 0.5f
#define QT 32
#define NKEY 96
#define WBACK 64
#define NB 4

// Scratch
__device__ __half g_Xh[NB * S_LEN * D_MODEL];   // X in fp16 (GEMM A + attn K)
__device__ __half g_Qh[NB * S_LEN * D_MODEL];   // Q fp16
__device__ __half g_Vh[NB * S_LEN * D_MODEL];   // V fp16 (+bias)
__device__ __half g_Wh[1024 * 512];             // [Wqk | Wv^T] fp16, [n][k]

// ---------------------------------------------------------------------------
// Helpers
// ---------------------------------------------------------------------------
__device__ __forceinline__ void mma16816h(float* d, const uint32_t* a,
                                          uint32_t b0, uint32_t b1)
{
    asm volatile(
        "mma.sync.aligned.m16n8k16.row.col.f32.f16.f16.f32 "
        "{%0,%1,%2,%3}, {%4,%5,%6,%7}, {%8,%9}, {%0,%1,%2,%3};"
        : "+f"(d[0]), "+f"(d[1]), "+f"(d[2]), "+f"(d[3])
        : "r"(a[0]), "r"(a[1]), "r"(a[2]), "r"(a[3]), "r"(b0), "r"(b1));
}

__device__ __forceinline__ void ldsm_x4_trans(uint32_t& r0, uint32_t& r1,
                                              uint32_t& r2, uint32_t& r3,
                                              uint32_t addr)
{
    asm volatile(
        "ldmatrix.sync.aligned.m8n8.x4.trans.shared.b16 {%0,%1,%2,%3}, [%4];"
        : "=r"(r0), "=r"(r1), "=r"(r2), "=r"(r3) : "r"(addr));
}

__device__ __forceinline__ void cpa16(uint32_t dst, const void* src) {
    asm volatile("cp.async.cg.shared.global [%0], [%1], 16;"
                 :: "r"(dst), "l"(src) : "memory");
}
__device__ __forceinline__ void sts_zero16(uint32_t dst) {
    asm volatile("st.shared.v4.b32 [%0], {%1,%1,%1,%1};" :: "r"(dst), "r"(0u)
                 : "memory");
}
#define CPA_COMMIT() asm volatile("cp.async.commit_group;" ::: "memory")
#define CPA_WAIT0()  asm volatile("cp.async.wait_group 0;" ::: "memory")

// ---------------------------------------------------------------------------
// pack_all: X -> fp16 (g_Xh), [Wqk | Wv^T] -> fp16 (g_Wh, [n][k])
// ---------------------------------------------------------------------------
__global__ void pack_all(const float* __restrict__ X,
                         const float* __restrict__ Wqk,
                         const float* __restrict__ Wv)
{
    int bid = blockIdx.x;
    if (bid < 8192) {
        int idx = bid * 256 + threadIdx.x;       // float4 over X
        float4 v = reinterpret_cast<const float4*>(X)[idx];
        __half2 h0 = __floats2half2_rn(v.x, v.y);
        __half2 h1 = __floats2half2_rn(v.z, v.w);
        uint2 t = make_uint2(*(uint32_t*)&h0, *(uint32_t*)&h1);
        *reinterpret_cast<uint2*>(&g_Xh[(size_t)idx * 4]) = t;
    } else {
        int idx = (bid - 8192) * 256 + threadIdx.x;   // 0..524287
        int n = idx >> 9, k = idx & 511;
        float w = (n < 512) ? Wqk[k * 512 + n] : Wv[(n - 512) * 512 + k];
        g_Wh[idx] = __float2half_rn(w);
    }
}

// ---------------------------------------------------------------------------
// fp16 mma GEMM: [Q|V][16384, 1024] = Xh[16384,512] @ Wh^T, m16n8k16.
// (R12 winner, verbatim.)
// ---------------------------------------------------------------------------
#define GSTR 36
#define GPLANE (128 * GSTR)

__global__ __launch_bounds__(256)
void mma_gemm(const float* __restrict__ bias,
              __half* __restrict__ Qh, __half* __restrict__ Vh)
{
    extern __shared__ uint32_t smw[];
    uint32_t* sA = smw;
    uint32_t* sB = smw + GPLANE;

    const int tid = threadIdx.x;
    const int wid = tid >> 5;
    const int lane = tid & 31;
    const int g = lane >> 2;
    const int t4 = lane & 3;
    const int warp_m = wid & 3;
    const int warp_n = wid >> 2;
    const int m0 = blockIdx.x * 128;
    const int n0 = blockIdx.y * 128;

    float acc[2][8][4];
#pragma unroll
    for (int mt = 0; mt < 2; mt++)
#pragma unroll
        for (int nt = 0; nt < 8; nt++)
#pragma unroll
            for (int i = 0; i < 4; i++) acc[mt][nt][i] = 0.f;

    for (int c = 0; c < 8; c++) {
        const int k0 = c * 64;     // in halves
        uint4 av[4], bv[4];
#pragma unroll
        for (int i = 0; i < 4; i++) {
            int idx = tid + 256 * i;
            int row = idx >> 3, h8 = (idx & 7) * 8;
            av[i] = *reinterpret_cast<const uint4*>(
                &g_Xh[(size_t)(m0 + row) * 512 + k0 + h8]);
            bv[i] = *reinterpret_cast<const uint4*>(
                &g_Wh[(size_t)(n0 + row) * 512 + k0 + h8]);
        }
        if (c) __syncthreads();
#pragma unroll
        for (int i = 0; i < 4; i++) {
            int idx = tid + 256 * i;
            int row = idx >> 3, w4 = (idx & 7) * 4;
            *reinterpret_cast<uint4*>(&sA[row * GSTR + w4]) = av[i];
            *reinterpret_cast<uint4*>(&sB[row * GSTR + w4]) = bv[i];
        }
        __syncthreads();

#pragma unroll
        for (int s = 0; s < 4; s++) {
            const int kc = s * 8 + t4;
            uint32_t a[2][4];
#pragma unroll
            for (int mt = 0; mt < 2; mt++) {
                int r = warp_m * 32 + mt * 16 + g;
                a[mt][0] = sA[r * GSTR + kc];
                a[mt][1] = sA[(r + 8) * GSTR + kc];
                a[mt][2] = sA[r * GSTR + kc + 4];
                a[mt][3] = sA[(r + 8) * GSTR + kc + 4];
            }
#pragma unroll
            for (int nt = 0; nt < 8; nt++) {
                int rn = warp_n * 64 + nt * 8 + g;
                uint32_t b0 = sB[rn * GSTR + kc];
                uint32_t b1 = sB[rn * GSTR + kc + 4];
#pragma unroll
                for (int mt = 0; mt < 2; mt++)
                    mma16816h(acc[mt][nt], a[mt], b0, b1);
            }
        }
    }

#pragma unroll
    for (int mt = 0; mt < 2; mt++) {
        int row0 = m0 + warp_m * 32 + mt * 16 + g;
#pragma unroll
        for (int nt = 0; nt < 8; nt++) {
            int col = n0 + warp_n * 64 + nt * 8 + t4 * 2;
            if (col < 512) {
                __half2 lo = __floats2half2_rn(acc[mt][nt][0], acc[mt][nt][1]);
                __half2 hi = __floats2half2_rn(acc[mt][nt][2], acc[mt][nt][3]);
                *reinterpret_cast<uint32_t*>(&Qh[(size_t)row0 * 512 + col]) =
                    *(uint32_t*)&lo;
                *reinterpret_cast<uint32_t*>(&Qh[(size_t)(row0 + 8) * 512 + col]) =
                    *(uint32_t*)&hi;
            } else {
                int vc = col - 512;
                float2 b2 = *reinterpret_cast<const float2*>(&bias[vc]);
                __half2 lo = __floats2half2_rn(acc[mt][nt][0] + b2.x,
                                               acc[mt][nt][1] + b2.y);
                __half2 hi = __floats2half2_rn(acc[mt][nt][2] + b2.x,
                                               acc[mt][nt][3] + b2.y);
                *reinterpret_cast<uint32_t*>(&Vh[(size_t)row0 * 512 + vc]) =
                    *(uint32_t*)&lo;
                *reinterpret_cast<uint32_t*>(&Vh[(size_t)(row0 + 8) * 512 + vc]) =
                    *(uint32_t*)&hi;
            }
        }
    }
}

// ---------------------------------------------------------------------------
// Windowed attention, all-fp16 MMA, band = 96 keys (WBACK 64).
// (R13's attention — validated numerically — on top of R12's producers.)
// CTA = 32 q x 96-key band, 8 warps (2m x 4n; 24 cols per n-warp).
// ---------------------------------------------------------------------------
#define SP_STR 100
#define PH_STR 52              // sPh row stride in words (48 pairs + pad)
#define HQ_STR 36              // phase-1 fp16 chunk row stride (words)
#define VH_STR 72              // phase-3 V row stride in halves
#define W_PH 3200
#define W_Q0 4864
#define W_K0 (W_Q0 + 32 * HQ_STR)        // 6016
#define W_Q1 (W_K0 + 96 * HQ_STR)        // 9472
#define W_K1 (W_Q1 + 32 * HQ_STR)        // 10624
#define W_V0 4864                        // aliased over phase-1 buffers
#define W_V1 (W_V0 + 96 * (VH_STR / 2))  // 8320
#define ATTN_W (W_K1 + 96 * HQ_STR)      // 14080 words = 56320 B

__global__ __launch_bounds__(256, 2)
void attn_tc(float* __restrict__ O)
{
    extern __shared__ uint32_t smw[];
    float* sP = reinterpret_cast<float*>(smw);
    uint32_t* sPh = smw + W_PH;
    const uint32_t sbase = (uint32_t)__cvta_generic_to_shared(smw);

    const int tid = threadIdx.x;
    const int wid = tid >> 5;
    const int lane = tid & 31;
    const int g = lane >> 2;
    const int t4 = lane & 3;
    const int b  = blockIdx.y;
    const int i0 = blockIdx.x * QT;
    const int jstart = i0 - WBACK;

    const __half* Qb = g_Qh + (size_t)b * S_LEN * D_MODEL;
    const __half* Kb = g_Xh + (size_t)b * S_LEN * D_MODEL;
    const __half* Vb = g_Vh + (size_t)b * S_LEN * D_MODEL;

    const int wm = wid & 1;
    const int wn = wid >> 1;      // 0..3 -> 24 score cols each

    const int qrow = tid >> 3;            // 0..31
    const int qu4  = tid & 7;

    // prologue: phase-1 chunk 0 (Q 32 rows, K 96 rows x 64 halves)
    {
        cpa16(sbase + (W_Q0 + qrow * HQ_STR + qu4 * 4) * 4,
              &Qb[(size_t)(i0 + qrow) * 512 + 0 + qu4 * 8]);
#pragma unroll
        for (int i = 0; i < 3; i++) {
            int idx = tid + 256 * i;      // 768 = 96 x 8
            int row = idx >> 3, u4 = idx & 7;
            int j = jstart + row;
            uint32_t dst = sbase + (W_K0 + row * HQ_STR + u4 * 4) * 4;
            if (j >= 0) cpa16(dst, &Kb[(size_t)j * 512 + 0 + u4 * 8]);
            else sts_zero16(dst);
        }
        CPA_COMMIT();
    }

    float accs[3][4];
#pragma unroll
    for (int nt = 0; nt < 3; nt++)
#pragma unroll
        for (int i = 0; i < 4; i++) accs[nt][i] = 0.f;

    for (int c = 0; c < 8; c++) {
        CPA_WAIT0();
        __syncthreads();
        if (c < 7) {
            const int k0 = (c + 1) * 64;
            const int wq = ((c + 1) & 1) ? W_Q1 : W_Q0;
            const int wk = ((c + 1) & 1) ? W_K1 : W_K0;
            cpa16(sbase + (wq + qrow * HQ_STR + qu4 * 4) * 4,
                  &Qb[(size_t)(i0 + qrow) * 512 + k0 + qu4 * 8]);
#pragma unroll
            for (int i = 0; i < 3; i++) {
                int idx = tid + 256 * i;
                int row = idx >> 3, u4 = idx & 7;
                int j = jstart + row;
                uint32_t dst = sbase + (wk + row * HQ_STR + u4 * 4) * 4;
                if (j >= 0) cpa16(dst, &Kb[(size_t)j * 512 + k0 + u4 * 8]);
                else sts_zero16(dst);
            }
            CPA_COMMIT();
        }
        const uint32_t* sQ = smw + ((c & 1) ? W_Q1 : W_Q0);
        const uint32_t* sK = smw + ((c & 1) ? W_K1 : W_K0);
#pragma unroll
        for (int s = 0; s < 4; s++) {
            const int kc = s * 8 + t4;
            uint32_t a[4];
            int r = wm * 16 + g;
            a[0] = sQ[r * HQ_STR + kc];
            a[1] = sQ[(r + 8) * HQ_STR + kc];
            a[2] = sQ[r * HQ_STR + kc + 4];
            a[3] = sQ[(r + 8) * HQ_STR + kc + 4];
#pragma unroll
            for (int nt = 0; nt < 3; nt++) {
                int rn = wn * 24 + nt * 8 + g;
                uint32_t b0 = sK[rn * HQ_STR + kc];
                uint32_t b1 = sK[rn * HQ_STR + kc + 4];
                mma16816h(accs[nt], a, b0, b1);
            }
        }
    }

    // scale + ALiBi + causal mask -> sP (fp32)
    const float scale = 0.04419417382415922f;
#pragma unroll
    for (int nt = 0; nt < 3; nt++) {
#pragma unroll
        for (int h = 0; h < 2; h++) {
            int row = wm * 16 + g + 8 * h;
            int i = i0 + row;
#pragma unroll
            for (int cp = 0; cp < 2; cp++) {
                int col = wn * 24 + nt * 8 + t4 * 2 + cp;
                int j = jstart + col;
                float v = accs[nt][h * 2 + cp];
                float s = (j < 0 || j > i) ? -1e30f
                        : v * scale + SLOPE * (float)(j - i);
                sP[row * SP_STR + col] = s;
            }
        }
    }
    __syncthreads();

    // ---- issue V chunk 0 (fp16, overlaps softmax) ----
    {
#pragma unroll
        for (int i = 0; i < 3; i++) {
            int idx = tid + 256 * i;          // 768 = 96 rows x 8
            int row = idx >> 3, u4 = idx & 7;
            int j = jstart + row;
            uint32_t dst = sbase + W_V0 * 4 + (row * VH_STR + u4 * 8) * 2;
            if (j >= 0) cpa16(dst, &Vb[(size_t)j * 512 + 0 + u4 * 8]);
            else sts_zero16(dst);
        }
        CPA_COMMIT();
    }

    // ---- softmax (96 cols: 8 lanes x 12); pack P fp16 pairs in sPh ----
    {
        int r = tid >> 3;
        int l = tid & 7;
        float* row = &sP[r * SP_STR];
        float m = -1e30f;
#pragma unroll
        for (int k = 0; k < 12; k++) m = fmaxf(m, row[l * 12 + k]);
#pragma unroll
        for (int o = 4; o > 0; o >>= 1)
            m = fmaxf(m, __shfl_xor_sync(0xffffffffu, m, o));
        float sum = 0.f;
        float e[12];
#pragma unroll
        for (int k = 0; k < 12; k++) {
            e[k] = __expf(row[l * 12 + k] - m);
            sum += e[k];
        }
#pragma unroll
        for (int o = 4; o > 0; o >>= 1)
            sum += __shfl_xor_sync(0xffffffffu, sum, o);
        float inv = 1.f / sum;
#pragma unroll
        for (int k = 0; k < 6; k++) {
            __half2 h2 = __floats2half2_rn(e[2 * k] * inv, e[2 * k + 1] * inv);
            sPh[r * PH_STR + l * 6 + k] = *(uint32_t*)&h2;
        }
    }
    __syncthreads();

    // ---- P fragments -> registers (6 k16 steps over 96 keys) ----
    uint32_t pa[6][4];
    {
        int r = wm * 16 + g;
#pragma unroll
        for (int s = 0; s < 6; s++) {
            int kc = s * 8 + t4;
            pa[s][0] = sPh[r * PH_STR + kc];
            pa[s][1] = sPh[(r + 8) * PH_STR + kc];
            pa[s][2] = sPh[r * PH_STR + kc + 4];
            pa[s][3] = sPh[(r + 8) * PH_STR + kc + 4];
        }
    }

    // ---- phase 3: O = P @ V (fp16 via ldmatrix.trans) ----
    const int wn8 = wid >> 1;          // 0..3 -> 16 features
    const int lrow = lane & 15;
    const int lcolg = (lane >> 4) * 8;

    for (int ch = 0; ch < 8; ch++) {
        CPA_WAIT0();
        __syncthreads();
        if (ch < 7) {
            const int e0 = (ch + 1) * 64;
            const int wv = ((ch + 1) & 1) ? W_V1 : W_V0;
#pragma unroll
            for (int i = 0; i < 3; i++) {
                int idx = tid + 256 * i;
                int row = idx >> 3, u4 = idx & 7;
                int j = jstart + row;
                uint32_t dst = sbase + wv * 4 + (row * VH_STR + u4 * 8) * 2;
                if (j >= 0) cpa16(dst, &Vb[(size_t)j * 512 + e0 + u4 * 8]);
                else sts_zero16(dst);
            }
            CPA_COMMIT();
        }
        const uint32_t vbase = sbase + ((ch & 1) ? W_V1 : W_V0) * 4;

        float acco[2][4];
#pragma unroll
        for (int nt = 0; nt < 2; nt++)
#pragma unroll
            for (int i = 0; i < 4; i++) acco[nt][i] = 0.f;

#pragma unroll
        for (int s = 0; s < 6; s++) {          // k16 over 96 tokens
            uint32_t r0, r1, r2, r3;
            uint32_t addr = vbase +
                ((s * 16 + lrow) * VH_STR + wn8 * 16 + lcolg) * 2;
            ldsm_x4_trans(r0, r1, r2, r3, addr);
            mma16816h(acco[0], pa[s], r0, r1);
            mma16816h(acco[1], pa[s], r2, r3);
        }

        const int e0 = ch * 64;
#pragma unroll
        for (int nt = 0; nt < 2; nt++) {
            int col = e0 + wn8 * 16 + nt * 8 + t4 * 2;
            int row0 = i0 + wm * 16 + g;
            *reinterpret_cast<float2*>(
                &O[((size_t)b * S_LEN + row0) * 512 + col]) =
                make_float2(acco[nt][0], acco[nt][1]);
            *reinterpret_cast<float2*>(
                &O[((size_t)b * S_LEN + row0 + 8) * 512 + col]) =
                make_float2(acco[nt][2], acco[nt][3]);
        }
    }
}

// ---------------------------------------------------------------------------
extern "C" void kernel_launch(void* const* d_in, const int* in_sizes, int n_in,
                              void* d_out, int out_size)
{
    const float* x   = (const float*)d_in[0];
    const float* Wqk = (const float*)d_in[1];
    const float* Wv  = (const float*)d_in[2];
    const float* bv  = (const float*)d_in[3];
    float* out = (float*)d_out;

    __half *Qhp = nullptr, *Vhp = nullptr;
    cudaGetSymbolAddress((void**)&Qhp, g_Qh);
    cudaGetSymbolAddress((void**)&Vhp, g_Vh);

    const int gemm_smem = 2 * GPLANE * 4;   // 36864 B
    cudaFuncSetAttribute(mma_gemm, cudaFuncAttributeMaxDynamicSharedMemorySize,
                         gemm_smem);
    const int attn_smem = ATTN_W * 4;       // 56320 B
    cudaFuncSetAttribute(attn_tc, cudaFuncAttributeMaxDynamicSharedMemorySize,
                         attn_smem);

    pack_all<<<10240, 256>>>(x, Wqk, Wv);

    dim3 ggemm(128, 8);
    mma_gemm<<<ggemm, 256, gemm_smem>>>(bv, Qhp, Vhp);

    dim3 gattn(S_LEN / QT, NB);
    attn_tc<<<gattn, 256, attn_smem>>>(out);
}